// round 16
// baseline (speedup 1.0000x reference)
#include <cuda_runtime.h>
#include <cuda_fp16.h>
#include <stdint.h>
#include <math.h>

#define BATCH 4
#define SEQ   2048
#define CDIM  768
#define NHEAD 12
#define HDIM  64
#define MROWS 8192
#define QKVDIM 2304
#define FCDIM  3072

typedef __half f16;

// ---------------- device scratch ----------------
__device__ f16   g_lnh[MROWS*CDIM];
__device__ f16   g_qkvh[MROWS*QKVDIM];
__device__ f16   g_atth[MROWS*CDIM];
__device__ float g_x1[MROWS*CDIM];
__device__ f16   g_fch[MROWS*FCDIM];
__device__ f16   g_wah[CDIM*QKVDIM];
__device__ f16   g_wph[CDIM*CDIM];
__device__ f16   g_wfh[CDIM*FCDIM];
__device__ f16   g_wmh[FCDIM*CDIM];

__device__ __forceinline__ uint32_t packh(float x, float y)
{
    __half2 t = __floats2half2_rn(x, y);
    return *(uint32_t*)&t;
}

__device__ __forceinline__ float ex2f(float x)
{
    float r;
    asm("ex2.approx.f32 %0, %1;" : "=f"(r) : "f"(x));
    return r;
}

// ---------------- cp.async helpers ----------------
__device__ __forceinline__ void cp16(void* s, const void* g)
{
    uint32_t a = (uint32_t)__cvta_generic_to_shared(s);
    asm volatile("cp.async.cg.shared.global [ %0 ], [ %1 ], 16;" :: "r"(a), "l"(g));
}

#define CP_COMMIT() asm volatile("cp.async.commit_group;")
#define CP_WAIT0()  asm volatile("cp.async.wait_group 0;")
#define CP_WAIT1()  asm volatile("cp.async.wait_group 1;")

// ---------------- fused fp32 -> fp16 conversion of all 4 weights ----------------
#define N1 (CDIM*QKVDIM/8)
#define N2 (CDIM*CDIM/8)
#define N3 (CDIM*FCDIM/8)
#define N4 (FCDIM*CDIM/8)

__global__ void cvt_all_kernel(const float* __restrict__ s1, f16* __restrict__ d1,
                               const float* __restrict__ s2, f16* __restrict__ d2,
                               const float* __restrict__ s3, f16* __restrict__ d3,
                               const float* __restrict__ s4, f16* __restrict__ d4)
{
    int i = blockIdx.x * 256 + threadIdx.x;
    const float* src;
    f16* dst;
    int j;
    if (i < N1) {
        src = s1; dst = d1; j = i;
    } else if (i < N1 + N2) {
        src = s2; dst = d2; j = i - N1;
    } else if (i < N1 + N2 + N3) {
        src = s3; dst = d3; j = i - N1 - N2;
    } else if (i < N1 + N2 + N3 + N4) {
        src = s4; dst = d4; j = i - N1 - N2 - N3;
    } else {
        return;
    }
    float4 a = ((const float4*)src)[2 * j];
    float4 b = ((const float4*)src)[2 * j + 1];
    __half2 h0 = __floats2half2_rn(a.x, a.y);
    __half2 h1 = __floats2half2_rn(a.z, a.w);
    __half2 h2 = __floats2half2_rn(b.x, b.y);
    __half2 h3 = __floats2half2_rn(b.z, b.w);
    uint4 o;
    o.x = *(uint32_t*)&h0;
    o.y = *(uint32_t*)&h1;
    o.z = *(uint32_t*)&h2;
    o.w = *(uint32_t*)&h3;
    ((uint4*)dst)[j] = o;
}

// ---------------- LayerNorm (single global read, fp16 output) ----------------
__global__ __launch_bounds__(256) void ln_kernel(
    const float* __restrict__ x, const float* __restrict__ gw,
    const float* __restrict__ gb, f16* __restrict__ oh)
{
    __shared__ float ss[8];
    __shared__ float ss2[8];
    int row = blockIdx.x;
    const float* xr = x + (size_t)row * CDIM;
    float xv[3];
    float s = 0.f, s2 = 0.f;
    #pragma unroll
    for (int j = 0; j < 3; j++) {
        xv[j] = xr[threadIdx.x + j * 256];
        s += xv[j];
        s2 += xv[j] * xv[j];
    }
    for (int o = 16; o > 0; o >>= 1) {
        s  += __shfl_xor_sync(0xFFFFFFFFu, s,  o);
        s2 += __shfl_xor_sync(0xFFFFFFFFu, s2, o);
    }
    int wid = threadIdx.x >> 5;
    int lane = threadIdx.x & 31;
    if (lane == 0) {
        ss[wid] = s;
        ss2[wid] = s2;
    }
    __syncthreads();
    if (threadIdx.x == 0) {
        float a = 0.f, a2 = 0.f;
        for (int i = 0; i < 8; i++) {
            a += ss[i];
            a2 += ss2[i];
        }
        ss[0] = a;
        ss2[0] = a2;
    }
    __syncthreads();
    float mean = ss[0] * (1.f / CDIM);
    float var  = ss2[0] * (1.f / CDIM) - mean * mean;
    if (var < 0.f) var = 0.f;
    float inv = 1.f / (sqrtf(var) + 1e-6f);
    #pragma unroll
    for (int j = 0; j < 3; j++) {
        int i = threadIdx.x + j * 256;
        float v = gw[i] * (xv[j] - mean) * inv + gb[i];
        oh[(size_t)row * CDIM + i] = __float2half_rn(v);
    }
}

// ---------------- mma helpers (asm operand lists spaced) ----------------
__device__ __forceinline__ void ldsm_x4(uint32_t* r, const void* p)
{
    uint32_t addr = (uint32_t)__cvta_generic_to_shared(p);
    asm volatile("ldmatrix.sync.aligned.m8n8.x4.shared.b16 { %0, %1, %2, %3 }, [ %4 ];"
        : "=r"(r[0]), "=r"(r[1]), "=r"(r[2]), "=r"(r[3]) : "r"(addr));
}

__device__ __forceinline__ void ldsm_x4_t(uint32_t* r, const void* p)
{
    uint32_t addr = (uint32_t)__cvta_generic_to_shared(p);
    asm volatile("ldmatrix.sync.aligned.m8n8.x4.trans.shared.b16 { %0, %1, %2, %3 }, [ %4 ];"
        : "=r"(r[0]), "=r"(r[1]), "=r"(r[2]), "=r"(r[3]) : "r"(addr));
}

__device__ __forceinline__ void mma_f16(float* c, const uint32_t* a,
                                        uint32_t b0, uint32_t b1)
{
    asm volatile("mma.sync.aligned.m16n8k16.row.col.f32.f16.f16.f32 "
        "{ %0, %1, %2, %3 }, { %4, %5, %6, %7 }, { %8, %9 }, { %0, %1, %2, %3 };"
        : "+f"(c[0]), "+f"(c[1]), "+f"(c[2]), "+f"(c[3])
        : "r"(a[0]), "r"(a[1]), "r"(a[2]), "r"(a[3]), "r"(b0), "r"(b1));
}

// ---------------- 128x128 fp16 tensor-core GEMM, 3-stage cp.async ----------------
// EPI: 1 = bias + GELU -> f16,  2 = bias + residual -> fp32,  3 = bias -> f16
#define HG_SMEM_BYTES (3 * (128 * 40 + 32 * 136) * 2)

#define HG_LOAD(s_, kk_) \
    cp16(&As[s_][rA0][cA0], Ahi + (size_t)(row0 + rA0) * K + (kk_) + cA0); \
    cp16(&As[s_][rA1][cA0], Ahi + (size_t)(row0 + rA1) * K + (kk_) + cA0); \
    cp16(&Bs[s_][rB0][cB0], Bhi + (size_t)((kk_) + rB0) * N + col0 + cB0); \
    cp16(&Bs[s_][rB1][cB0], Bhi + (size_t)((kk_) + rB1) * N + col0 + cB0); \
    CP_COMMIT()

template<int EPI>
__global__ __launch_bounds__(256, 2) void hgemm(
    const f16* __restrict__ Ahi,
    const f16* __restrict__ Bhi,
    const float* __restrict__ bias, const float* __restrict__ res,
    float* __restrict__ Cf, f16* __restrict__ Chi,
    int M, int N, int K)
{
    extern __shared__ f16 dsm[];
    f16 (*As)[128][40] = reinterpret_cast<f16 (*)[128][40]>(dsm);
    f16 (*Bs)[32][136] = reinterpret_cast<f16 (*)[32][136]>(dsm + 3 * 128 * 40);

    const int tid  = threadIdx.x;
    const int lane = tid & 31;
    const int warp = tid >> 5;
    const int wm = (warp >> 1) * 32;
    const int wn = (warp & 1) * 64;
    const int row0 = blockIdx.y * 128;
    const int col0 = blockIdx.x * 128;

    const int rA0 = tid >> 2;
    const int cA0 = (tid & 3) * 8;
    const int rA1 = rA0 + 64;
    const int rB0 = tid >> 4;
    const int cB0 = (tid & 15) * 8;
    const int rB1 = rB0 + 16;

    const int KT = K / 32;

    float acc[2][8][4];
    #pragma unroll
    for (int i = 0; i < 2; i++) {
        #pragma unroll
        for (int j = 0; j < 8; j++) {
            #pragma unroll
            for (int e = 0; e < 4; e++) {
                acc[i][j][e] = 0.f;
            }
        }
    }

    HG_LOAD(0, 0);
    HG_LOAD(1, 32);

    for (int it = 0; it < KT; ++it) {
        if (it + 1 < KT) {
            CP_WAIT1();
        } else {
            CP_WAIT0();
        }
        __syncthreads();
        if (it + 2 < KT) {
            HG_LOAD((it + 2) % 3, (it + 2) * 32);
        }
        const int s = it % 3;

        #pragma unroll
        for (int ks = 0; ks < 2; ++ks) {
            const int k0 = ks * 16;
            uint32_t af0[4];
            uint32_t af1[4];
            ldsm_x4(af0, &As[s][wm + (lane & 15)][k0 + (lane >> 4) * 8]);
            ldsm_x4(af1, &As[s][wm + 16 + (lane & 15)][k0 + (lane >> 4) * 8]);
            #pragma unroll
            for (int ni = 0; ni < 4; ++ni) {
                uint32_t bb[4];
                ldsm_x4_t(bb, &Bs[s][k0 + (lane & 15)][wn + ni * 16 + (lane >> 4) * 8]);
                mma_f16(acc[0][ni * 2 + 0], af0, bb[0], bb[1]);
                mma_f16(acc[0][ni * 2 + 1], af0, bb[2], bb[3]);
                mma_f16(acc[1][ni * 2 + 0], af1, bb[0], bb[1]);
                mma_f16(acc[1][ni * 2 + 1], af1, bb[2], bb[3]);
            }
        }
    }

    #pragma unroll
    for (int mi = 0; mi < 2; ++mi) {
        #pragma unroll
        for (int n8 = 0; n8 < 8; ++n8) {
            #pragma unroll
            for (int half = 0; half < 2; ++half) {
                int r = row0 + wm + mi * 16 + (lane >> 2) + half * 8;
                int c = col0 + wn + n8 * 8 + (lane & 3) * 2;
                float v0 = acc[mi][n8][half * 2 + 0] + bias[c];
                float v1 = acc[mi][n8][half * 2 + 1] + bias[c + 1];
                size_t off = (size_t)r * N + c;
                if (EPI == 1) {
                    v0 = 0.5f * v0 * (1.f + erff(v0 * 0.7071067811865475f));
                    v1 = 0.5f * v1 * (1.f + erff(v1 * 0.7071067811865475f));
                    *(uint32_t*)(Chi + off) = packh(v0, v1);
                } else if (EPI == 3) {
                    *(uint32_t*)(Chi + off) = packh(v0, v1);
                } else {
                    float2 rv = *(const float2*)(res + off);
                    float2 ov;
                    ov.x = v0 + rv.x;
                    ov.y = v1 + rv.y;
                    *(float2*)(Cf + off) = ov;
                }
            }
        }
    }
}

// ---------------- Tensor-core flash attention (causal, fp16, Br=128) ----------------
// grid: (SEQ/128, NHEAD, BATCH), 256 threads = 8 warps; warp owns 16 query rows.
// Scores in log2 domain (0.125*log2e folded into Q frags) -> bare ex2 softmax.
// Fully-masked diagonal warp-tiles skip all compute (bit-identical: p == 0).
#define ATT_SMEM ((128 * 72 + 2 * 64 * 72 + 2 * 64 * 72) * 2)

#define ATT_LOAD(s_, kt_) \
    _Pragma("unroll") \
    for (int li = 0; li < 2; li++) { \
        int e2 = tid + li * 256; \
        int r2 = e2 >> 3; \
        int c2 = (e2 & 7) * 8; \
        size_t goff2 = base + (size_t)((kt_) * 64 + r2) * QKVDIM + CDIM + h * HDIM + c2; \
        cp16(&KsH[s_][r2][c2], qkvh + goff2); \
        cp16(&Vs[s_][r2][c2], qkvh + goff2 + CDIM); \
    } \
    CP_COMMIT()

__global__ __launch_bounds__(256, 2) void fattn_kernel(
    const f16* __restrict__ qkvh, f16* __restrict__ outh)
{
    extern __shared__ f16 attsm[];
    f16 (*Qs)[72] = reinterpret_cast<f16 (*)[72]>(attsm);
    f16 (*KsH)[64][72] = reinterpret_cast<f16 (*)[64][72]>(attsm + 128 * 72);
    f16 (*Vs)[64][72]  = reinterpret_cast<f16 (*)[64][72]>(attsm + 128 * 72 + 2 * 64 * 72);

    const int b = blockIdx.z;
    const int h = blockIdx.y;
    const int qb = (SEQ / 128 - 1) - blockIdx.x;   // longest first
    const int tid = threadIdx.x;
    const int lane = tid & 31;
    const int warp = tid >> 5;
    const int row0 = qb * 128;

    const size_t base = (size_t)b * SEQ * QKVDIM;
    // 0.125 * log2(e): scores come out of the mma already in the log2 domain
    const float QSC = 0.18033688011112042f;
    const __half2 sc2 = __floats2half2_rn(QSC, QSC);

    ATT_LOAD(0, 0);

    #pragma unroll
    for (int i = 0; i < 4; i++) {
        int e = tid + i * 256;
        int r = e >> 3;
        int c = (e & 7) * 8;
        *(uint4*)&Qs[r][c] = *(const uint4*)(qkvh + base + (size_t)(row0 + r) * QKVDIM + h * HDIM + c);
    }
    __syncthreads();
    uint32_t qh[4][4];
    #pragma unroll
    for (int kf = 0; kf < 4; kf++) {
        ldsm_x4(qh[kf], &Qs[warp * 16 + (lane & 15)][kf * 16 + (lane >> 4) * 8]);
        #pragma unroll
        for (int e = 0; e < 4; e++) {
            __half2 t = *(__half2*)&qh[kf][e];
            t = __hmul2(t, sc2);
            qh[kf][e] = *(uint32_t*)&t;
        }
    }

    float oacc[8][4];
    #pragma unroll
    for (int nb = 0; nb < 8; nb++) {
        #pragma unroll
        for (int e = 0; e < 4; e++) {
            oacc[nb][e] = 0.f;
        }
    }
    float m1 = -1e30f, m2 = -1e30f;
    float l1 = 0.f, l2 = 0.f;

    const int r1g = row0 + warp * 16 + (lane >> 2);
    const int r2g = r1g + 8;
    const int wmaxrow = row0 + warp * 16 + 15;   // last query row owned by this warp
    const int ntiles = 2 * qb + 2;

    for (int kt = 0; kt < ntiles; kt++) {
        const int j0g = kt * 64;
        CP_WAIT0();
        __syncthreads();
        if (kt + 1 < ntiles) {
            ATT_LOAD((kt + 1) & 1, kt + 1);
        }
        const int s = kt & 1;

        // fully-masked tile for this warp: every p underflows to exactly 0 -> skip
        if (j0g > wmaxrow) {
            continue;
        }

        float sacc[8][4];
        #pragma unroll
        for (int nb = 0; nb < 8; nb++) {
            #pragma unroll
            for (int e = 0; e < 4; e++) {
                sacc[nb][e] = 0.f;
            }
        }
        #pragma unroll
        for (int kf = 0; kf < 4; kf++) {
            const int d0 = kf * 16;
            #pragma unroll
            for (int p = 0; p < 4; p++) {
                const int j0 = p * 16;
                uint32_t bh[4];
                ldsm_x4(bh, &KsH[s][j0 + ((lane >> 4) << 3) + (lane & 7)][d0 + (((lane >> 3) & 1) << 3)]);
                mma_f16(sacc[p * 2 + 0], qh[kf], bh[0], bh[1]);
                mma_f16(sacc[p * 2 + 1], qh[kf], bh[2], bh[3]);
            }
        }

        if (kt >= 2 * qb) {
            #pragma unroll
            for (int nb = 0; nb < 8; nb++) {
                int jg = j0g + nb * 8 + (lane & 3) * 2;
                if (jg     > r1g) sacc[nb][0] = -1e30f;
                if (jg + 1 > r1g) sacc[nb][1] = -1e30f;
                if (jg     > r2g) sacc[nb][2] = -1e30f;
                if (jg + 1 > r2g) sacc[nb][3] = -1e30f;
            }
        }

        float mx1 = -1e30f, mx2 = -1e30f;
        #pragma unroll
        for (int nb = 0; nb < 8; nb++) {
            mx1 = fmaxf(mx1, fmaxf(sacc[nb][0], sacc[nb][1]));
            mx2 = fmaxf(mx2, fmaxf(sacc[nb][2], sacc[nb][3]));
        }
        mx1 = fmaxf(mx1, __shfl_xor_sync(0xFFFFFFFFu, mx1, 1));
        mx1 = fmaxf(mx1, __shfl_xor_sync(0xFFFFFFFFu, mx1, 2));
        mx2 = fmaxf(mx2, __shfl_xor_sync(0xFFFFFFFFu, mx2, 1));
        mx2 = fmaxf(mx2, __shfl_xor_sync(0xFFFFFFFFu, mx2, 2));

        const uint32_t stable = __all_sync(0xFFFFFFFFu, (mx1 <= m1) && (mx2 <= m2));

        if (!stable) {
            float om1 = m1;
            float om2 = m2;
            m1 = fmaxf(m1, mx1);
            m2 = fmaxf(m2, mx2);
            float co1 = ex2f(om1 - m1);
            float co2 = ex2f(om2 - m2);
            l1 *= co1;
            l2 *= co2;
            #pragma unroll
            for (int nb = 0; nb < 8; nb++) {
                oacc[nb][0] *= co1;
                oacc[nb][1] *= co1;
                oacc[nb][2] *= co2;
                oacc[nb][3] *= co2;
            }
        }

        uint32_t pa1[8];
        uint32_t pa2[8];
        float ps1 = 0.f, ps2 = 0.f;
        #pragma unroll
        for (int nb = 0; nb < 8; nb++) {
            float p0 = ex2f(sacc[nb][0] - m1);
            float p1 = ex2f(sacc[nb][1] - m1);
            float p2 = ex2f(sacc[nb][2] - m2);
            float p3 = ex2f(sacc[nb][3] - m2);
            ps1 += p0 + p1;
            ps2 += p2 + p3;
            pa1[nb] = packh(p0, p1);
            pa2[nb] = packh(p2, p3);
        }
        l1 += ps1;
        l2 += ps2;

        #pragma unroll
        for (int kf = 0; kf < 4; kf++) {
            uint32_t af[4];
            af[0] = pa1[kf * 2];
            af[1] = pa2[kf * 2];
            af[2] = pa1[kf * 2 + 1];
            af[3] = pa2[kf * 2 + 1];
            #pragma unroll
            for (int pd = 0; pd < 4; pd++) {
                uint32_t bb[4];
                ldsm_x4_t(bb, &Vs[s][kf * 16 + (lane & 15)][pd * 16 + (lane >> 4) * 8]);
                mma_f16(oacc[pd * 2 + 0], af, bb[0], bb[1]);
                mma_f16(oacc[pd * 2 + 1], af, bb[2], bb[3]);
            }
        }
    }

    l1 += __shfl_xor_sync(0xFFFFFFFFu, l1, 1);
    l1 += __shfl_xor_sync(0xFFFFFFFFu, l1, 2);
    l2 += __shfl_xor_sync(0xFFFFFFFFu, l2, 1);
    l2 += __shfl_xor_sync(0xFFFFFFFFu, l2, 2);
    float inv1 = 1.f / l1;
    float inv2 = 1.f / l2;

    size_t ob1 = (size_t)(b * SEQ + r1g) * CDIM + h * HDIM;
    size_t ob2 = (size_t)(b * SEQ + r2g) * CDIM + h * HDIM;
    #pragma unroll
    for (int nb = 0; nb < 8; nb++) {
        int c = nb * 8 + (lane & 3) * 2;
        *(uint32_t*)(outh + ob1 + c) = packh(oacc[nb][0] * inv1, oacc[nb][1] * inv1);
        *(uint32_t*)(outh + ob2 + c) = packh(oacc[nb][2] * inv2, oacc[nb][3] * inv2);
    }
}

// ---------------- launch ----------------
extern "C" void kernel_launch(void* const* d_in, const int* in_sizes, int n_in,
                              void* d_out, int out_size)
{
    const float* x           = (const float*)d_in[0];
    const float* ln1_w       = (const float*)d_in[1];
    const float* ln1_b       = (const float*)d_in[2];
    const float* W_attn      = (const float*)d_in[3];
    const float* b_attn      = (const float*)d_in[4];
    const float* W_attn_proj = (const float*)d_in[5];
    const float* b_attn_proj = (const float*)d_in[6];
    const float* ln2_w       = (const float*)d_in[7];
    const float* ln2_b       = (const float*)d_in[8];
    const float* W_fc        = (const float*)d_in[9];
    const float* b_fc        = (const float*)d_in[10];
    const float* W_mlp_proj  = (const float*)d_in[11];
    const float* b_mlp_proj  = (const float*)d_in[12];
    float* out = (float*)d_out;

    f16 *p_lnh, *p_qkvh, *p_atth, *p_fch;
    f16 *p_wah, *p_wph, *p_wfh, *p_wmh;
    float *p_x1;
    cudaGetSymbolAddress((void**)&p_lnh,  g_lnh);
    cudaGetSymbolAddress((void**)&p_qkvh, g_qkvh);
    cudaGetSymbolAddress((void**)&p_atth, g_atth);
    cudaGetSymbolAddress((void**)&p_x1,   g_x1);
    cudaGetSymbolAddress((void**)&p_fch,  g_fch);
    cudaGetSymbolAddress((void**)&p_wah,  g_wah);
    cudaGetSymbolAddress((void**)&p_wph,  g_wph);
    cudaGetSymbolAddress((void**)&p_wfh,  g_wfh);
    cudaGetSymbolAddress((void**)&p_wmh,  g_wmh);

    cudaFuncSetAttribute(hgemm<1>, cudaFuncAttributeMaxDynamicSharedMemorySize, HG_SMEM_BYTES);
    cudaFuncSetAttribute(hgemm<2>, cudaFuncAttributeMaxDynamicSharedMemorySize, HG_SMEM_BYTES);
    cudaFuncSetAttribute(hgemm<3>, cudaFuncAttributeMaxDynamicSharedMemorySize, HG_SMEM_BYTES);
    cudaFuncSetAttribute(fattn_kernel, cudaFuncAttributeMaxDynamicSharedMemorySize, ATT_SMEM);

    const int cvt_total = N1 + N2 + N3 + N4;
    cvt_all_kernel<<<(cvt_total + 255) / 256, 256>>>(W_attn, p_wah, W_attn_proj, p_wph,
                                                     W_fc, p_wfh, W_mlp_proj, p_wmh);

    ln_kernel<<<MROWS, 256>>>(x, ln1_w, ln1_b, p_lnh);

    hgemm<3><<<dim3(QKVDIM / 128, MROWS / 128), 256, HG_SMEM_BYTES>>>(p_lnh, p_wah,
        b_attn, (const float*)0, (float*)0, p_qkvh, MROWS, QKVDIM, CDIM);

    fattn_kernel<<<dim3(SEQ / 128, NHEAD, BATCH), 256, ATT_SMEM>>>(p_qkvh, p_atth);

    hgemm<2><<<dim3(CDIM / 128, MROWS / 128), 256, HG_SMEM_BYTES>>>(p_atth, p_wph,
        b_attn_proj, x, p_x1, (f16*)0, MROWS, CDIM, CDIM);

    ln_kernel<<<MROWS, 256>>>(p_x1, ln2_w, ln2_b, p_lnh);

    hgemm<1><<<dim3(FCDIM / 128, MROWS / 128), 256, HG_SMEM_BYTES>>>(p_lnh, p_wfh,
        b_fc, (const float*)0, (float*)0, p_fch, MROWS, FCDIM, CDIM);

    hgemm<2><<<dim3(CDIM / 128, MROWS / 128), 256, HG_SMEM_BYTES>>>(p_fch, p_wmh,
        b_mlp_proj, p_x1, out, (f16*)0, MROWS, CDIM, FCDIM);
}

// round 17
// speedup vs baseline: 1.0110x; 1.0110x over previous
#include <cuda_runtime.h>
#include <cuda_fp16.h>
#include <stdint.h>
#include <math.h>

#define BATCH 4
#define SEQ   2048
#define CDIM  768
#define NHEAD 12
#define HDIM  64
#define MROWS 8192
#define QKVDIM 2304
#define FCDIM  3072

typedef __half f16;

// ---------------- device scratch ----------------
__device__ f16   g_lnh[MROWS*CDIM];
__device__ f16   g_qkvh[MROWS*QKVDIM];
__device__ f16   g_atth[MROWS*CDIM];
__device__ float g_x1[MROWS*CDIM];
__device__ f16   g_fch[MROWS*FCDIM];
__device__ f16   g_wah[CDIM*QKVDIM];
__device__ f16   g_wph[CDIM*CDIM];
__device__ f16   g_wfh[CDIM*FCDIM];
__device__ f16   g_wmh[FCDIM*CDIM];

__device__ __forceinline__ uint32_t packh(float x, float y)
{
    __half2 t = __floats2half2_rn(x, y);
    return *(uint32_t*)&t;
}

__device__ __forceinline__ float ex2f(float x)
{
    float r;
    asm("ex2.approx.f32 %0, %1;" : "=f"(r) : "f"(x));
    return r;
}

__device__ __forceinline__ uint32_t h2ex2(uint32_t x)
{
    uint32_t r;
    asm("ex2.approx.f16x2 %0, %1;" : "=r"(r) : "r"(x));
    return r;
}

// ---------------- cp.async helpers ----------------
__device__ __forceinline__ void cp16(void* s, const void* g)
{
    uint32_t a = (uint32_t)__cvta_generic_to_shared(s);
    asm volatile("cp.async.cg.shared.global [ %0 ], [ %1 ], 16;" :: "r"(a), "l"(g));
}

#define CP_COMMIT() asm volatile("cp.async.commit_group;")
#define CP_WAIT0()  asm volatile("cp.async.wait_group 0;")
#define CP_WAIT1()  asm volatile("cp.async.wait_group 1;")

// ---------------- fused fp32 -> fp16 conversion of all 4 weights ----------------
#define N1 (CDIM*QKVDIM/8)
#define N2 (CDIM*CDIM/8)
#define N3 (CDIM*FCDIM/8)
#define N4 (FCDIM*CDIM/8)

__global__ void cvt_all_kernel(const float* __restrict__ s1, f16* __restrict__ d1,
                               const float* __restrict__ s2, f16* __restrict__ d2,
                               const float* __restrict__ s3, f16* __restrict__ d3,
                               const float* __restrict__ s4, f16* __restrict__ d4)
{
    int i = blockIdx.x * 256 + threadIdx.x;
    const float* src;
    f16* dst;
    int j;
    if (i < N1) {
        src = s1; dst = d1; j = i;
    } else if (i < N1 + N2) {
        src = s2; dst = d2; j = i - N1;
    } else if (i < N1 + N2 + N3) {
        src = s3; dst = d3; j = i - N1 - N2;
    } else if (i < N1 + N2 + N3 + N4) {
        src = s4; dst = d4; j = i - N1 - N2 - N3;
    } else {
        return;
    }
    float4 a = ((const float4*)src)[2 * j];
    float4 b = ((const float4*)src)[2 * j + 1];
    __half2 h0 = __floats2half2_rn(a.x, a.y);
    __half2 h1 = __floats2half2_rn(a.z, a.w);
    __half2 h2 = __floats2half2_rn(b.x, b.y);
    __half2 h3 = __floats2half2_rn(b.z, b.w);
    uint4 o;
    o.x = *(uint32_t*)&h0;
    o.y = *(uint32_t*)&h1;
    o.z = *(uint32_t*)&h2;
    o.w = *(uint32_t*)&h3;
    ((uint4*)dst)[j] = o;
}

// ---------------- LayerNorm (single global read, fp16 output) ----------------
__global__ __launch_bounds__(256) void ln_kernel(
    const float* __restrict__ x, const float* __restrict__ gw,
    const float* __restrict__ gb, f16* __restrict__ oh)
{
    __shared__ float ss[8];
    __shared__ float ss2[8];
    int row = blockIdx.x;
    const float* xr = x + (size_t)row * CDIM;
    float xv[3];
    float s = 0.f, s2 = 0.f;
    #pragma unroll
    for (int j = 0; j < 3; j++) {
        xv[j] = xr[threadIdx.x + j * 256];
        s += xv[j];
        s2 += xv[j] * xv[j];
    }
    for (int o = 16; o > 0; o >>= 1) {
        s  += __shfl_xor_sync(0xFFFFFFFFu, s,  o);
        s2 += __shfl_xor_sync(0xFFFFFFFFu, s2, o);
    }
    int wid = threadIdx.x >> 5;
    int lane = threadIdx.x & 31;
    if (lane == 0) {
        ss[wid] = s;
        ss2[wid] = s2;
    }
    __syncthreads();
    if (threadIdx.x == 0) {
        float a = 0.f, a2 = 0.f;
        for (int i = 0; i < 8; i++) {
            a += ss[i];
            a2 += ss2[i];
        }
        ss[0] = a;
        ss2[0] = a2;
    }
    __syncthreads();
    float mean = ss[0] * (1.f / CDIM);
    float var  = ss2[0] * (1.f / CDIM) - mean * mean;
    if (var < 0.f) var = 0.f;
    float inv = 1.f / (sqrtf(var) + 1e-6f);
    #pragma unroll
    for (int j = 0; j < 3; j++) {
        int i = threadIdx.x + j * 256;
        float v = gw[i] * (xv[j] - mean) * inv + gb[i];
        oh[(size_t)row * CDIM + i] = __float2half_rn(v);
    }
}

// ---------------- mma helpers (asm operand lists spaced) ----------------
__device__ __forceinline__ void ldsm_x4(uint32_t* r, const void* p)
{
    uint32_t addr = (uint32_t)__cvta_generic_to_shared(p);
    asm volatile("ldmatrix.sync.aligned.m8n8.x4.shared.b16 { %0, %1, %2, %3 }, [ %4 ];"
        : "=r"(r[0]), "=r"(r[1]), "=r"(r[2]), "=r"(r[3]) : "r"(addr));
}

__device__ __forceinline__ void ldsm_x4_t(uint32_t* r, const void* p)
{
    uint32_t addr = (uint32_t)__cvta_generic_to_shared(p);
    asm volatile("ldmatrix.sync.aligned.m8n8.x4.trans.shared.b16 { %0, %1, %2, %3 }, [ %4 ];"
        : "=r"(r[0]), "=r"(r[1]), "=r"(r[2]), "=r"(r[3]) : "r"(addr));
}

__device__ __forceinline__ void mma_f16(float* c, const uint32_t* a,
                                        uint32_t b0, uint32_t b1)
{
    asm volatile("mma.sync.aligned.m16n8k16.row.col.f32.f16.f16.f32 "
        "{ %0, %1, %2, %3 }, { %4, %5, %6, %7 }, { %8, %9 }, { %0, %1, %2, %3 };"
        : "+f"(c[0]), "+f"(c[1]), "+f"(c[2]), "+f"(c[3])
        : "r"(a[0]), "r"(a[1]), "r"(a[2]), "r"(a[3]), "r"(b0), "r"(b1));
}

// ---------------- 128x128 fp16 tensor-core GEMM, 3-stage cp.async ----------------
// EPI: 1 = bias + GELU -> f16,  2 = bias + residual -> fp32,  3 = bias -> f16
#define HG_SMEM_BYTES (3 * (128 * 40 + 32 * 136) * 2)

#define HG_LOAD(s_, kk_) \
    cp16(&As[s_][rA0][cA0], Ahi + (size_t)(row0 + rA0) * K + (kk_) + cA0); \
    cp16(&As[s_][rA1][cA0], Ahi + (size_t)(row0 + rA1) * K + (kk_) + cA0); \
    cp16(&Bs[s_][rB0][cB0], Bhi + (size_t)((kk_) + rB0) * N + col0 + cB0); \
    cp16(&Bs[s_][rB1][cB0], Bhi + (size_t)((kk_) + rB1) * N + col0 + cB0); \
    CP_COMMIT()

template<int EPI>
__global__ __launch_bounds__(256, 2) void hgemm(
    const f16* __restrict__ Ahi,
    const f16* __restrict__ Bhi,
    const float* __restrict__ bias, const float* __restrict__ res,
    float* __restrict__ Cf, f16* __restrict__ Chi,
    int M, int N, int K)
{
    extern __shared__ f16 dsm[];
    f16 (*As)[128][40] = reinterpret_cast<f16 (*)[128][40]>(dsm);
    f16 (*Bs)[32][136] = reinterpret_cast<f16 (*)[32][136]>(dsm + 3 * 128 * 40);

    const int tid  = threadIdx.x;
    const int lane = tid & 31;
    const int warp = tid >> 5;
    const int wm = (warp >> 1) * 32;
    const int wn = (warp & 1) * 64;
    const int row0 = blockIdx.y * 128;
    const int col0 = blockIdx.x * 128;

    const int rA0 = tid >> 2;
    const int cA0 = (tid & 3) * 8;
    const int rA1 = rA0 + 64;
    const int rB0 = tid >> 4;
    const int cB0 = (tid & 15) * 8;
    const int rB1 = rB0 + 16;

    const int KT = K / 32;

    float acc[2][8][4];
    #pragma unroll
    for (int i = 0; i < 2; i++) {
        #pragma unroll
        for (int j = 0; j < 8; j++) {
            #pragma unroll
            for (int e = 0; e < 4; e++) {
                acc[i][j][e] = 0.f;
            }
        }
    }

    HG_LOAD(0, 0);
    HG_LOAD(1, 32);

    for (int it = 0; it < KT; ++it) {
        if (it + 1 < KT) {
            CP_WAIT1();
        } else {
            CP_WAIT0();
        }
        __syncthreads();
        if (it + 2 < KT) {
            HG_LOAD((it + 2) % 3, (it + 2) * 32);
        }
        const int s = it % 3;

        #pragma unroll
        for (int ks = 0; ks < 2; ++ks) {
            const int k0 = ks * 16;
            uint32_t af0[4];
            uint32_t af1[4];
            ldsm_x4(af0, &As[s][wm + (lane & 15)][k0 + (lane >> 4) * 8]);
            ldsm_x4(af1, &As[s][wm + 16 + (lane & 15)][k0 + (lane >> 4) * 8]);
            #pragma unroll
            for (int ni = 0; ni < 4; ++ni) {
                uint32_t bb[4];
                ldsm_x4_t(bb, &Bs[s][k0 + (lane & 15)][wn + ni * 16 + (lane >> 4) * 8]);
                mma_f16(acc[0][ni * 2 + 0], af0, bb[0], bb[1]);
                mma_f16(acc[0][ni * 2 + 1], af0, bb[2], bb[3]);
                mma_f16(acc[1][ni * 2 + 0], af1, bb[0], bb[1]);
                mma_f16(acc[1][ni * 2 + 1], af1, bb[2], bb[3]);
            }
        }
    }

    #pragma unroll
    for (int mi = 0; mi < 2; ++mi) {
        #pragma unroll
        for (int n8 = 0; n8 < 8; ++n8) {
            #pragma unroll
            for (int half = 0; half < 2; ++half) {
                int r = row0 + wm + mi * 16 + (lane >> 2) + half * 8;
                int c = col0 + wn + n8 * 8 + (lane & 3) * 2;
                float v0 = acc[mi][n8][half * 2 + 0] + bias[c];
                float v1 = acc[mi][n8][half * 2 + 1] + bias[c + 1];
                size_t off = (size_t)r * N + c;
                if (EPI == 1) {
                    v0 = 0.5f * v0 * (1.f + erff(v0 * 0.7071067811865475f));
                    v1 = 0.5f * v1 * (1.f + erff(v1 * 0.7071067811865475f));
                    *(uint32_t*)(Chi + off) = packh(v0, v1);
                } else if (EPI == 3) {
                    *(uint32_t*)(Chi + off) = packh(v0, v1);
                } else {
                    float2 rv = *(const float2*)(res + off);
                    float2 ov;
                    ov.x = v0 + rv.x;
                    ov.y = v1 + rv.y;
                    *(float2*)(Cf + off) = ov;
                }
            }
        }
    }
}

// ---------------- Tensor-core flash attention (causal, fp16, Br=128) ----------------
// grid: (SEQ/128, NHEAD, BATCH), 256 threads = 8 warps; warp owns 16 query rows.
// Scores in log2 domain (0.125*log2e folded into Q) -> packed ex2.f16x2 softmax;
// l accumulated on the tensor pipe via ones-mma (full row reduction, fp32).
#define ATT_SMEM ((128 * 72 + 2 * 64 * 72 + 2 * 64 * 72) * 2)
#define ONE2 0x3C003C00u

#define ATT_LOAD(s_, kt_) \
    _Pragma("unroll") \
    for (int li = 0; li < 2; li++) { \
        int e2 = tid + li * 256; \
        int r2 = e2 >> 3; \
        int c2 = (e2 & 7) * 8; \
        size_t goff2 = base + (size_t)((kt_) * 64 + r2) * QKVDIM + CDIM + h * HDIM + c2; \
        cp16(&KsH[s_][r2][c2], qkvh + goff2); \
        cp16(&Vs[s_][r2][c2], qkvh + goff2 + CDIM); \
    } \
    CP_COMMIT()

__global__ __launch_bounds__(256, 2) void fattn_kernel(
    const f16* __restrict__ qkvh, f16* __restrict__ outh)
{
    extern __shared__ f16 attsm[];
    f16 (*Qs)[72] = reinterpret_cast<f16 (*)[72]>(attsm);
    f16 (*KsH)[64][72] = reinterpret_cast<f16 (*)[64][72]>(attsm + 128 * 72);
    f16 (*Vs)[64][72]  = reinterpret_cast<f16 (*)[64][72]>(attsm + 128 * 72 + 2 * 64 * 72);

    const int b = blockIdx.z;
    const int h = blockIdx.y;
    const int qb = (SEQ / 128 - 1) - blockIdx.x;   // longest first
    const int tid = threadIdx.x;
    const int lane = tid & 31;
    const int warp = tid >> 5;
    const int row0 = qb * 128;

    const size_t base = (size_t)b * SEQ * QKVDIM;
    const float QSC = 0.18033688011112042f;   // 0.125 * log2(e)
    const __half2 sc2 = __floats2half2_rn(QSC, QSC);

    ATT_LOAD(0, 0);

    #pragma unroll
    for (int i = 0; i < 4; i++) {
        int e = tid + i * 256;
        int r = e >> 3;
        int c = (e & 7) * 8;
        *(uint4*)&Qs[r][c] = *(const uint4*)(qkvh + base + (size_t)(row0 + r) * QKVDIM + h * HDIM + c);
    }
    __syncthreads();
    uint32_t qh[4][4];
    #pragma unroll
    for (int kf = 0; kf < 4; kf++) {
        ldsm_x4(qh[kf], &Qs[warp * 16 + (lane & 15)][kf * 16 + (lane >> 4) * 8]);
        #pragma unroll
        for (int e = 0; e < 4; e++) {
            __half2 t = *(__half2*)&qh[kf][e];
            t = __hmul2(t, sc2);
            qh[kf][e] = *(uint32_t*)&t;
        }
    }

    float oacc[8][4];
    #pragma unroll
    for (int nb = 0; nb < 8; nb++) {
        #pragma unroll
        for (int e = 0; e < 4; e++) {
            oacc[nb][e] = 0.f;
        }
    }
    float lacc[4];
    #pragma unroll
    for (int e = 0; e < 4; e++) {
        lacc[e] = 0.f;
    }
    float m1 = -1e30f, m2 = -1e30f;

    const int r1g = row0 + warp * 16 + (lane >> 2);
    const int r2g = r1g + 8;
    const int wmaxrow = row0 + warp * 16 + 15;
    const int ntiles = 2 * qb + 2;

    for (int kt = 0; kt < ntiles; kt++) {
        const int j0g = kt * 64;
        CP_WAIT0();
        __syncthreads();
        if (kt + 1 < ntiles) {
            ATT_LOAD((kt + 1) & 1, kt + 1);
        }
        const int s = kt & 1;

        if (j0g > wmaxrow) {
            continue;
        }

        // ---- S = Q K^T ----
        float sacc[8][4];
        #pragma unroll
        for (int nb = 0; nb < 8; nb++) {
            #pragma unroll
            for (int e = 0; e < 4; e++) {
                sacc[nb][e] = 0.f;
            }
        }
        #pragma unroll
        for (int kf = 0; kf < 4; kf++) {
            const int d0 = kf * 16;
            #pragma unroll
            for (int p = 0; p < 4; p++) {
                const int j0 = p * 16;
                uint32_t bh[4];
                ldsm_x4(bh, &KsH[s][j0 + ((lane >> 4) << 3) + (lane & 7)][d0 + (((lane >> 3) & 1) << 3)]);
                mma_f16(sacc[p * 2 + 0], qh[kf], bh[0], bh[1]);
                mma_f16(sacc[p * 2 + 1], qh[kf], bh[2], bh[3]);
            }
        }

        if (kt >= 2 * qb) {
            #pragma unroll
            for (int nb = 0; nb < 8; nb++) {
                int jg = j0g + nb * 8 + (lane & 3) * 2;
                if (jg     > r1g) sacc[nb][0] = -1e30f;
                if (jg + 1 > r1g) sacc[nb][1] = -1e30f;
                if (jg     > r2g) sacc[nb][2] = -1e30f;
                if (jg + 1 > r2g) sacc[nb][3] = -1e30f;
            }
        }

        // ---- online softmax (log2 domain, packed exp) ----
        float mx1 = -1e30f, mx2 = -1e30f;
        #pragma unroll
        for (int nb = 0; nb < 8; nb++) {
            mx1 = fmaxf(mx1, fmaxf(sacc[nb][0], sacc[nb][1]));
            mx2 = fmaxf(mx2, fmaxf(sacc[nb][2], sacc[nb][3]));
        }
        mx1 = fmaxf(mx1, __shfl_xor_sync(0xFFFFFFFFu, mx1, 1));
        mx1 = fmaxf(mx1, __shfl_xor_sync(0xFFFFFFFFu, mx1, 2));
        mx2 = fmaxf(mx2, __shfl_xor_sync(0xFFFFFFFFu, mx2, 1));
        mx2 = fmaxf(mx2, __shfl_xor_sync(0xFFFFFFFFu, mx2, 2));

        const uint32_t stable = __all_sync(0xFFFFFFFFu, (mx1 <= m1) && (mx2 <= m2));

        if (!stable) {
            float om1 = m1;
            float om2 = m2;
            m1 = fmaxf(m1, mx1);
            m2 = fmaxf(m2, mx2);
            float co1 = ex2f(om1 - m1);
            float co2 = ex2f(om2 - m2);
            lacc[0] *= co1;
            lacc[1] *= co1;
            lacc[2] *= co2;
            lacc[3] *= co2;
            #pragma unroll
            for (int nb = 0; nb < 8; nb++) {
                oacc[nb][0] *= co1;
                oacc[nb][1] *= co1;
                oacc[nb][2] *= co2;
                oacc[nb][3] *= co2;
            }
        }

        uint32_t pa1[8];
        uint32_t pa2[8];
        #pragma unroll
        for (int nb = 0; nb < 8; nb++) {
            pa1[nb] = h2ex2(packh(sacc[nb][0] - m1, sacc[nb][1] - m1));
            pa2[nb] = h2ex2(packh(sacc[nb][2] - m2, sacc[nb][3] - m2));
        }

        // ---- O += P V ; l += P 1 (ones-mma: full row reduction, fp32) ----
        #pragma unroll
        for (int kf = 0; kf < 4; kf++) {
            uint32_t af[4];
            af[0] = pa1[kf * 2];
            af[1] = pa2[kf * 2];
            af[2] = pa1[kf * 2 + 1];
            af[3] = pa2[kf * 2 + 1];
            #pragma unroll
            for (int pd = 0; pd < 4; pd++) {
                uint32_t bb[4];
                ldsm_x4_t(bb, &Vs[s][kf * 16 + (lane & 15)][pd * 16 + (lane >> 4) * 8]);
                mma_f16(oacc[pd * 2 + 0], af, bb[0], bb[1]);
                mma_f16(oacc[pd * 2 + 1], af, bb[2], bb[3]);
            }
            mma_f16(lacc, af, ONE2, ONE2);
        }
    }

    // ---- finalize (lacc already holds full row sums) ----
    float inv1 = 1.f / lacc[0];
    float inv2 = 1.f / lacc[2];

    size_t ob1 = (size_t)(b * SEQ + r1g) * CDIM + h * HDIM;
    size_t ob2 = (size_t)(b * SEQ + r2g) * CDIM + h * HDIM;
    #pragma unroll
    for (int nb = 0; nb < 8; nb++) {
        int c = nb * 8 + (lane & 3) * 2;
        *(uint32_t*)(outh + ob1 + c) = packh(oacc[nb][0] * inv1, oacc[nb][1] * inv1);
        *(uint32_t*)(outh + ob2 + c) = packh(oacc[nb][2] * inv2, oacc[nb][3] * inv2);
    }
}

// ---------------- launch ----------------
extern "C" void kernel_launch(void* const* d_in, const int* in_sizes, int n_in,
                              void* d_out, int out_size)
{
    const float* x           = (const float*)d_in[0];
    const float* ln1_w       = (const float*)d_in[1];
    const float* ln1_b       = (const float*)d_in[2];
    const float* W_attn      = (const float*)d_in[3];
    const float* b_attn      = (const float*)d_in[4];
    const float* W_attn_proj = (const float*)d_in[5];
    const float* b_attn_proj = (const float*)d_in[6];
    const float* ln2_w       = (const float*)d_in[7];
    const float* ln2_b       = (const float*)d_in[8];
    const float* W_fc        = (const float*)d_in[9];
    const float* b_fc        = (const float*)d_in[10];
    const float* W_mlp_proj  = (const float*)d_in[11];
    const float* b_mlp_proj  = (const float*)d_in[12];
    float* out = (float*)d_out;

    f16 *p_lnh, *p_qkvh, *p_atth, *p_fch;
    f16 *p_wah, *p_wph, *p_wfh, *p_wmh;
    float *p_x1;
    cudaGetSymbolAddress((void**)&p_lnh,  g_lnh);
    cudaGetSymbolAddress((void**)&p_qkvh, g_qkvh);
    cudaGetSymbolAddress((void**)&p_atth, g_atth);
    cudaGetSymbolAddress((void**)&p_x1,   g_x1);
    cudaGetSymbolAddress((void**)&p_fch,  g_fch);
    cudaGetSymbolAddress((void**)&p_wah,  g_wah);
    cudaGetSymbolAddress((void**)&p_wph,  g_wph);
    cudaGetSymbolAddress((void**)&p_wfh,  g_wfh);
    cudaGetSymbolAddress((void**)&p_wmh,  g_wmh);

    cudaFuncSetAttribute(hgemm<1>, cudaFuncAttributeMaxDynamicSharedMemorySize, HG_SMEM_BYTES);
    cudaFuncSetAttribute(hgemm<2>, cudaFuncAttributeMaxDynamicSharedMemorySize, HG_SMEM_BYTES);
    cudaFuncSetAttribute(hgemm<3>, cudaFuncAttributeMaxDynamicSharedMemorySize, HG_SMEM_BYTES);
    cudaFuncSetAttribute(fattn_kernel, cudaFuncAttributeMaxDynamicSharedMemorySize, ATT_SMEM);

    const int cvt_total = N1 + N2 + N3 + N4;
    cvt_all_kernel<<<(cvt_total + 255) / 256, 256>>>(W_attn, p_wah, W_attn_proj, p_wph,
                                                     W_fc, p_wfh, W_mlp_proj, p_wmh);

    ln_kernel<<<MROWS, 256>>>(x, ln1_w, ln1_b, p_lnh);

    hgemm<3><<<dim3(QKVDIM / 128, MROWS / 128), 256, HG_SMEM_BYTES>>>(p_lnh, p_wah,
        b_attn, (const float*)0, (float*)0, p_qkvh, MROWS, QKVDIM, CDIM);

    fattn_kernel<<<dim3(SEQ / 128, NHEAD, BATCH), 256, ATT_SMEM>>>(p_qkvh, p_atth);

    hgemm<2><<<dim3(CDIM / 128, MROWS / 128), 256, HG_SMEM_BYTES>>>(p_atth, p_wph,
        b_attn_proj, x, p_x1, (f16*)0, MROWS, CDIM, CDIM);

    ln_kernel<<<MROWS, 256>>>(p_x1, ln2_w, ln2_b, p_lnh);

    hgemm<1><<<dim3(FCDIM / 128, MROWS / 128), 256, HG_SMEM_BYTES>>>(p_lnh, p_wfh,
        b_fc, (const float*)0, (float*)0, p_fch, MROWS, FCDIM, CDIM);

    hgemm<2><<<dim3(CDIM / 128, MROWS / 128), 256, HG_SMEM_BYTES>>>(p_fch, p_wmh,
        b_mlp_proj, p_x1, out, (f16*)0, MROWS, CDIM, FCDIM);
}